// round 10
// baseline (speedup 1.0000x reference)
#include <cuda_runtime.h>
#include <cuda_fp16.h>
#include <cstdint>

// ===================== problem dims =====================
#define M_DIM 8192      // B*S = 4*2048
#define N_DIM 16384
#define K_DIM 4096

#define BM 128
#define BN 128
#define BK 64                         // halves per K-chunk (128 bytes per row)
#define NCHUNK (K_DIM / BK)           // 64
#define STAGES 3
#define THREADS 128                   // 4 warps, 64x64 warp tiles
#define TILES_M (M_DIM / BM)          // 64
#define TILES_N (N_DIM / BN)          // 128
#define NTILES  (TILES_M * TILES_N)   // 8192
#define GROUP_M 32                    // raster: m-tiles per group (2 exact passes over B)

// ===================== scratch (alloc-free) =====================
__device__ __half g_A[(size_t)M_DIM * K_DIM];   // 64 MB fp16 activations
__device__ __half g_B[(size_t)N_DIM * K_DIM];   // 128 MB fp16 weights (exact int8 values)

// ===================== PTX helpers (baseline features only) =====================
__device__ __forceinline__ uint32_t smem_to_u32(const void* p) {
    uint32_t a;
    asm("{ .reg .u64 t; cvta.to.shared.u64 t, %1; cvt.u32.u64 %0, t; }" : "=r"(a) : "l"(p));
    return a;
}
__device__ __forceinline__ void cp_async16(uint32_t dst, const void* src) {
    asm volatile("cp.async.cg.shared.global [%0], [%1], 16;" :: "r"(dst), "l"(src));
}
__device__ __forceinline__ void cp_commit() {
    asm volatile("cp.async.commit_group;" ::: "memory");
}
template <int N>
__device__ __forceinline__ void cp_wait() {
    asm volatile("cp.async.wait_group %0;" :: "n"(N) : "memory");
}
__device__ __forceinline__ void ldsm_x4(uint32_t* r, uint32_t addr) {
    asm volatile("ldmatrix.sync.aligned.m8n8.x4.shared.b16 {%0,%1,%2,%3}, [%4];"
                 : "=r"(r[0]), "=r"(r[1]), "=r"(r[2]), "=r"(r[3]) : "r"(addr));
}
__device__ __forceinline__ void mma16816(float* d, const uint32_t* a, const uint32_t* b) {
    asm volatile(
        "mma.sync.aligned.m16n8k16.row.col.f32.f16.f16.f32 "
        "{%0,%1,%2,%3}, {%4,%5,%6,%7}, {%8,%9}, {%0,%1,%2,%3};"
        : "+f"(d[0]), "+f"(d[1]), "+f"(d[2]), "+f"(d[3])
        : "r"(a[0]), "r"(a[1]), "r"(a[2]), "r"(a[3]), "r"(b[0]), "r"(b[1]));
}

// SW128 swizzle for 128B rows: 16B chunk index ^= (row & 7)
__device__ __forceinline__ uint32_t swz_row_col(int row, int colbytes) {
    return (uint32_t)(row * 128) + (uint32_t)(colbytes ^ ((row & 7) << 4));
}

// raster: m fastest within groups of GROUP_M m-tiles
__device__ __forceinline__ void tile_coords(int t, int& tm, int& tn) {
    const int per_group = GROUP_M * TILES_N;           // 4096
    const int g  = t / per_group;
    const int r_ = t % per_group;
    tm = (g * GROUP_M + (r_ % GROUP_M)) * BM;
    tn = (r_ / GROUP_M) * BN;
}

// ===================== SMEM layout =====================
#define A_STAGE_BYTES (BM * 128)              // 16384
#define B_STAGE_BYTES (BN * 128)              // 16384
#define STAGE_BYTES   (A_STAGE_BYTES + B_STAGE_BYTES)   // 32768
#define SMEM_BODY     (STAGES * STAGE_BYTES)  // 98304
#define SMEM_TOTAL    (SMEM_BODY + 128)       // manual 128B alignment headroom

// ===================== fused conversion kernel =====================
// blocks [0, 16384):  fp32 -> fp16 activations (8 elems/thread)
// blocks [16384, 49152): int32 -> fp16 weights  (8 elems/thread)
struct alignas(16) H8 { __half2 a, b, c, d; };

#define CVT_A_BLOCKS 16384
#define CVT_W_BLOCKS 32768

__global__ void cvt_kernel(const float4* __restrict__ inA, const int4* __restrict__ inW) {
    if (blockIdx.x < CVT_A_BLOCKS) {
        size_t i = (size_t)blockIdx.x * blockDim.x + threadIdx.x;
        float4 v0 = inA[2 * i];
        float4 v1 = inA[2 * i + 1];
        H8 h;
        h.a = __floats2half2_rn(v0.x, v0.y);
        h.b = __floats2half2_rn(v0.z, v0.w);
        h.c = __floats2half2_rn(v1.x, v1.y);
        h.d = __floats2half2_rn(v1.z, v1.w);
        reinterpret_cast<H8*>(g_A)[i] = h;
    } else {
        size_t i = (size_t)(blockIdx.x - CVT_A_BLOCKS) * blockDim.x + threadIdx.x;
        int4 v0 = inW[2 * i];
        int4 v1 = inW[2 * i + 1];
        H8 h;
        h.a = __floats2half2_rn((float)v0.x, (float)v0.y);
        h.b = __floats2half2_rn((float)v0.z, (float)v0.w);
        h.c = __floats2half2_rn((float)v1.x, (float)v1.y);
        h.d = __floats2half2_rn((float)v1.z, (float)v1.w);
        reinterpret_cast<H8*>(g_B)[i] = h;
    }
}

// ===================== persistent GEMM kernel =====================
__global__ void __launch_bounds__(THREADS, 2)
gemm_f16_hmma(float* __restrict__ out,
              const float* __restrict__ scale,
              const float* __restrict__ bias) {
    extern __shared__ char smem_raw[];
    char* smem = (char*)(((uintptr_t)smem_raw + 127) & ~(uintptr_t)127);
    const uint32_t sb = smem_to_u32(smem);

    const int tid  = threadIdx.x;
    const int wid  = tid >> 5;
    const int lane = tid & 31;
    const int wm   = wid >> 1;   // 0..1  (m-warp, 64 rows)
    const int wn   = wid & 1;    // 0..1  (n-warp, 64 cols)
    const int nb   = gridDim.x;

    // ldmatrix per-lane row/col-sub mappings (validated round-2/5 logic)
    const int rowA_in16 = ((lane >> 3) & 1) * 8 + (lane & 7);
    const int ksubA     = ((lane >> 4) & 1) * 16;
    const int rowB_in16 = ((lane >> 4) & 1) * 8 + (lane & 7);
    const int ksubB     = ((lane >> 3) & 1) * 16;

    // per-thread cp.async coordinates (idx = tid + j*128 ; r = idx>>3, c = idx&7)
    const int cp_r0 = tid >> 3;            // rows advance by 16 per j
    const int cp_c  = tid & 7;

    float acc[4][8][4];
    #pragma unroll
    for (int mt = 0; mt < 4; mt++)
        #pragma unroll
        for (int nt = 0; nt < 8; nt++)
            #pragma unroll
            for (int q = 0; q < 4; q++) acc[mt][nt][q] = 0.0f;

    // ---- fragment loader for one k16 step ----
    auto load_frags = [&](uint32_t sA, uint32_t sB, int ks,
                          uint32_t a[4][4], uint32_t b[8][2]) {
        #pragma unroll
        for (int mt = 0; mt < 4; mt++) {
            const int row = wm * 64 + mt * 16 + rowA_in16;
            ldsm_x4(a[mt], sA + swz_row_col(row, ks * 32 + ksubA));
        }
        #pragma unroll
        for (int p = 0; p < 4; p++) {
            const int row = wn * 64 + p * 16 + rowB_in16;
            uint32_t r4[4];
            ldsm_x4(r4, sB + swz_row_col(row, ks * 32 + ksubB));
            b[2 * p][0] = r4[0]; b[2 * p][1] = r4[1];
            b[2 * p + 1][0] = r4[2]; b[2 * p + 1][1] = r4[3];
        }
    };

    // ---- first tile + prologue ----
    int t = blockIdx.x;
    if (t >= NTILES) return;
    int tile_m, tile_n;
    tile_coords(t, tile_m, tile_n);
    const __half* aG = g_A + (size_t)tile_m * K_DIM;
    const __half* bG = g_B + (size_t)tile_n * K_DIM;

    #pragma unroll
    for (int s = 0; s < STAGES - 1; s++) {
        const uint32_t sA = sb + s * STAGE_BYTES;
        const uint32_t sB = sA + A_STAGE_BYTES;
        const int kh = s * BK;
        #pragma unroll
        for (int j = 0; j < 8; j++) {
            int r = cp_r0 + j * 16;
            cp_async16(sA + swz_row_col(r, cp_c * 16), aG + (size_t)r * K_DIM + kh + cp_c * 8);
        }
        #pragma unroll
        for (int j = 0; j < 8; j++) {
            int r = cp_r0 + j * 16;
            cp_async16(sB + swz_row_col(r, cp_c * 16), bG + (size_t)r * K_DIM + kh + cp_c * 8);
        }
        cp_commit();
    }
    cp_wait<STAGES - 2>();
    __syncthreads();

    int cstage = 0;                        // stage being consumed
    int lstage = STAGES - 1;               // stage being filled

    // ---- persistent tile loop; producer chunk-stream continues across tiles ----
    while (true) {
        const int  tnext   = t + nb;
        const bool hasNext = (tnext < NTILES);
        int tmn = 0, tnn = 0;
        const __half* aGn = aG;
        const __half* bGn = bG;
        if (hasNext) {
            tile_coords(tnext, tmn, tnn);
            aGn = g_A + (size_t)tmn * K_DIM;
            bGn = g_B + (size_t)tnn * K_DIM;
        }

        for (int kc = 0; kc < NCHUNK; kc++) {
            // producer chunk (current tile tail, or head of next tile)
            const int  kload  = kc + STAGES - 1;
            const __half* pA;
            const __half* pB;
            int  khl;
            bool doLoad;
            if (kload < NCHUNK) {
                pA = aG; pB = bG; khl = kload * BK; doLoad = true;
            } else {
                pA = aGn; pB = bGn; khl = (kload - NCHUNK) * BK; doLoad = hasNext;
            }
            const uint32_t lA = sb + lstage * STAGE_BYTES;
            const uint32_t lB = lA + A_STAGE_BYTES;

            const uint32_t sA = sb + cstage * STAGE_BYTES;
            const uint32_t sB = sA + A_STAGE_BYTES;

            uint32_t afrag[2][4][4];
            uint32_t bfrag[2][8][2];
            load_frags(sA, sB, 0, afrag[0], bfrag[0]);

            #pragma unroll
            for (int ks = 0; ks < 4; ks++) {
                const int cur = ks & 1;
                // prefetch next k16 fragments before issuing MMAs
                if (ks < 3) load_frags(sA, sB, ks + 1, afrag[cur ^ 1], bfrag[cur ^ 1]);

                // interleave 4 cp.async (2 A-slices + 2 B-slices) for the prefetch chunk
                if (doLoad) {
                    #pragma unroll
                    for (int q = 0; q < 2; q++) {
                        int r = cp_r0 + (ks * 2 + q) * 16;
                        cp_async16(lA + swz_row_col(r, cp_c * 16),
                                   pA + (size_t)r * K_DIM + khl + cp_c * 8);
                        cp_async16(lB + swz_row_col(r, cp_c * 16),
                                   pB + (size_t)r * K_DIM + khl + cp_c * 8);
                    }
                }

                #pragma unroll
                for (int mt = 0; mt < 4; mt++)
                    #pragma unroll
                    for (int nt = 0; nt < 8; nt++)
                        mma16816(acc[mt][nt], afrag[cur][mt], bfrag[cur][nt]);
            }
            cp_commit();

            cp_wait<STAGES - 2>();
            __syncthreads();

            if (++cstage == STAGES) cstage = 0;
            if (++lstage == STAGES) lstage = 0;
        }

        // ---- epilogue for tile t: scale * acc + bias, direct float2 stores ----
        {
            const int colbase = tile_n + wn * 64 + (lane & 3) * 2;
            float2 sc[8], bi[8];
            #pragma unroll
            for (int nt = 0; nt < 8; nt++) {
                sc[nt] = *reinterpret_cast<const float2*>(scale + colbase + nt * 8);
                bi[nt] = *reinterpret_cast<const float2*>(bias  + colbase + nt * 8);
            }

            #pragma unroll
            for (int mt = 0; mt < 4; mt++) {
                const int grow = tile_m + wm * 64 + mt * 16 + (lane >> 2);
                float* o0 = out + (size_t)grow * N_DIM + colbase;
                float* o1 = o0 + (size_t)8 * N_DIM;
                #pragma unroll
                for (int nt = 0; nt < 8; nt++) {
                    float2 v0, v1;
                    v0.x = acc[mt][nt][0] * sc[nt].x + bi[nt].x;
                    v0.y = acc[mt][nt][1] * sc[nt].y + bi[nt].y;
                    v1.x = acc[mt][nt][2] * sc[nt].x + bi[nt].x;
                    v1.y = acc[mt][nt][3] * sc[nt].y + bi[nt].y;
                    *reinterpret_cast<float2*>(o0 + nt * 8) = v0;
                    *reinterpret_cast<float2*>(o1 + nt * 8) = v1;
                    acc[mt][nt][0] = 0.0f; acc[mt][nt][1] = 0.0f;
                    acc[mt][nt][2] = 0.0f; acc[mt][nt][3] = 0.0f;
                }
            }
        }

        if (!hasNext) break;
        t = tnext; tile_m = tmn; tile_n = tnn; aG = aGn; bG = bGn;
    }
}

// ===================== launch =====================
extern "C" void kernel_launch(void* const* d_in, const int* in_sizes, int n_in,
                              void* d_out, int out_size) {
    const float* inp  = (const float*)d_in[0];   // (4, 2048, 4096) f32
    const int*   wgt  = (const int*)d_in[1];     // (16384, 4096) int32 (int8-valued)
    const float* wsc  = (const float*)d_in[2];   // (16384,) f32
    const float* bias = (const float*)d_in[3];   // (16384,) f32
    float* out = (float*)d_out;                  // (4, 2048, 16384) f32

    (void)in_sizes; (void)n_in; (void)out_size;

    cvt_kernel<<<CVT_A_BLOCKS + CVT_W_BLOCKS, 256>>>(
        reinterpret_cast<const float4*>(inp), reinterpret_cast<const int4*>(wgt));

    int dev = 0, smc = 148;
    cudaGetDevice(&dev);
    cudaDeviceGetAttribute(&smc, cudaDevAttrMultiProcessorCount, dev);
    int nblocks = 2 * smc;
    if (nblocks > NTILES) nblocks = NTILES;

    cudaFuncSetAttribute(gemm_f16_hmma,
                         cudaFuncAttributeMaxDynamicSharedMemorySize, SMEM_TOTAL);
    gemm_f16_hmma<<<nblocks, THREADS, SMEM_TOTAL>>>(out, wsc, bias);
}

// round 11
// speedup vs baseline: 1.2272x; 1.2272x over previous
#include <cuda_runtime.h>
#include <cuda_fp16.h>
#include <cstdint>

// ===================== problem dims =====================
#define M_DIM 8192      // B*S = 4*2048
#define N_DIM 16384
#define K_DIM 4096

#define BM 128
#define BN 128
#define BK 64                         // halves per K-chunk (128 bytes per row)
#define NCHUNK (K_DIM / BK)           // 64
#define STAGES 3
#define THREADS 128                   // 4 warps, 64x64 warp tiles
#define TILES_M (M_DIM / BM)          // 64
#define TILES_N (N_DIM / BN)          // 128
#define GROUP_M 32                    // raster: m-tiles per group (2 exact passes over B)

// ===================== scratch (alloc-free) =====================
__device__ __half g_A[(size_t)M_DIM * K_DIM];   // 64 MB fp16 activations
__device__ __half g_B[(size_t)N_DIM * K_DIM];   // 128 MB fp16 weights (exact int8 values)

// ===================== PTX helpers (baseline features only) =====================
__device__ __forceinline__ uint32_t smem_to_u32(const void* p) {
    uint32_t a;
    asm("{ .reg .u64 t; cvta.to.shared.u64 t, %1; cvt.u32.u64 %0, t; }" : "=r"(a) : "l"(p));
    return a;
}
__device__ __forceinline__ void cp_async16(uint32_t dst, const void* src) {
    asm volatile("cp.async.cg.shared.global [%0], [%1], 16;" :: "r"(dst), "l"(src));
}
__device__ __forceinline__ void cp_commit() {
    asm volatile("cp.async.commit_group;" ::: "memory");
}
template <int N>
__device__ __forceinline__ void cp_wait() {
    asm volatile("cp.async.wait_group %0;" :: "n"(N) : "memory");
}
__device__ __forceinline__ void ldsm_x4(uint32_t* r, uint32_t addr) {
    asm volatile("ldmatrix.sync.aligned.m8n8.x4.shared.b16 {%0,%1,%2,%3}, [%4];"
                 : "=r"(r[0]), "=r"(r[1]), "=r"(r[2]), "=r"(r[3]) : "r"(addr));
}
__device__ __forceinline__ void mma16816(float* d, const uint32_t* a, const uint32_t* b) {
    asm volatile(
        "mma.sync.aligned.m16n8k16.row.col.f32.f16.f16.f32 "
        "{%0,%1,%2,%3}, {%4,%5,%6,%7}, {%8,%9}, {%0,%1,%2,%3};"
        : "+f"(d[0]), "+f"(d[1]), "+f"(d[2]), "+f"(d[3])
        : "r"(a[0]), "r"(a[1]), "r"(a[2]), "r"(a[3]), "r"(b[0]), "r"(b[1]));
}
// streaming (evict-first) float2 store — keeps B stripe resident in L2
__device__ __forceinline__ void stg_cs_f2(float* p, float x, float y) {
    asm volatile("st.global.cs.v2.f32 [%0], {%1, %2};" :: "l"(p), "f"(x), "f"(y) : "memory");
}

// SW128 swizzle for 128B rows: 16B chunk index ^= (row & 7)
__device__ __forceinline__ uint32_t swz_row_col(int row, int colbytes) {
    return (uint32_t)(row * 128) + (uint32_t)(colbytes ^ ((row & 7) << 4));
}

// ===================== SMEM layout =====================
#define A_STAGE_BYTES (BM * 128)              // 16384
#define B_STAGE_BYTES (BN * 128)              // 16384
#define STAGE_BYTES   (A_STAGE_BYTES + B_STAGE_BYTES)   // 32768
#define SMEM_BODY     (STAGES * STAGE_BYTES)  // 98304
#define SMEM_TOTAL    (SMEM_BODY + 128)       // manual 128B alignment headroom

// ===================== fused conversion kernel =====================
struct alignas(16) H8 { __half2 a, b, c, d; };

#define CVT_A_BLOCKS 16384
#define CVT_W_BLOCKS 32768

__global__ void cvt_kernel(const float4* __restrict__ inA, const int4* __restrict__ inW) {
    if (blockIdx.x < CVT_A_BLOCKS) {
        size_t i = (size_t)blockIdx.x * blockDim.x + threadIdx.x;
        float4 v0 = inA[2 * i];
        float4 v1 = inA[2 * i + 1];
        H8 h;
        h.a = __floats2half2_rn(v0.x, v0.y);
        h.b = __floats2half2_rn(v0.z, v0.w);
        h.c = __floats2half2_rn(v1.x, v1.y);
        h.d = __floats2half2_rn(v1.z, v1.w);
        reinterpret_cast<H8*>(g_A)[i] = h;
    } else {
        size_t i = (size_t)(blockIdx.x - CVT_A_BLOCKS) * blockDim.x + threadIdx.x;
        int4 v0 = inW[2 * i];
        int4 v1 = inW[2 * i + 1];
        H8 h;
        h.a = __floats2half2_rn((float)v0.x, (float)v0.y);
        h.b = __floats2half2_rn((float)v0.z, (float)v0.w);
        h.c = __floats2half2_rn((float)v1.x, (float)v1.y);
        h.d = __floats2half2_rn((float)v1.z, (float)v1.w);
        reinterpret_cast<H8*>(g_B)[i] = h;
    }
}

// ===================== GEMM kernel (round-9 champion + streaming stores) =====================
__global__ void __launch_bounds__(THREADS, 2)
gemm_f16_hmma(float* __restrict__ out,
              const float* __restrict__ scale,
              const float* __restrict__ bias) {
    extern __shared__ char smem_raw[];
    char* smem = (char*)(((uintptr_t)smem_raw + 127) & ~(uintptr_t)127);
    const uint32_t sb = smem_to_u32(smem);

    const int tid  = threadIdx.x;
    const int wid  = tid >> 5;
    const int lane = tid & 31;
    const int wm   = wid >> 1;   // 0..1  (m-warp, 64 rows)
    const int wn   = wid & 1;    // 0..1  (n-warp, 64 cols)

    // ---- CTA raster swizzle: m fastest within groups of GROUP_M m-tiles ----
    const int bid       = blockIdx.x;
    const int per_group = GROUP_M * TILES_N;           // 4096
    const int g         = bid / per_group;
    const int r_        = bid % per_group;
    const int tile_m    = (g * GROUP_M + (r_ % GROUP_M)) * BM;
    const int tile_n    = (r_ / GROUP_M) * BN;

    const __half* aG = g_A + (size_t)tile_m * K_DIM;
    const __half* bG = g_B + (size_t)tile_n * K_DIM;

    // ldmatrix per-lane row/col-sub mappings (validated round-2/5 logic)
    const int rowA_in16 = ((lane >> 3) & 1) * 8 + (lane & 7);
    const int ksubA     = ((lane >> 4) & 1) * 16;
    const int rowB_in16 = ((lane >> 4) & 1) * 8 + (lane & 7);
    const int ksubB     = ((lane >> 3) & 1) * 16;

    // per-thread cp.async coordinates (idx = tid + j*128 ; r = idx>>3, c = idx&7)
    const int cp_r0 = tid >> 3;            // rows advance by 16 per j
    const int cp_c  = tid & 7;

    float acc[4][8][4];
    #pragma unroll
    for (int mt = 0; mt < 4; mt++)
        #pragma unroll
        for (int nt = 0; nt < 8; nt++)
            #pragma unroll
            for (int q = 0; q < 4; q++) acc[mt][nt][q] = 0.0f;

    // ---- full-chunk producer (prologue only) ----
    auto load_stage_full = [&](int stage, int kc) {
        const uint32_t sA = sb + stage * STAGE_BYTES;
        const uint32_t sB = sA + A_STAGE_BYTES;
        const int kh = kc * BK;
        #pragma unroll
        for (int j = 0; j < 8; j++) {
            int r = cp_r0 + j * 16;
            cp_async16(sA + swz_row_col(r, cp_c * 16), aG + (size_t)r * K_DIM + kh + cp_c * 8);
        }
        #pragma unroll
        for (int j = 0; j < 8; j++) {
            int r = cp_r0 + j * 16;
            cp_async16(sB + swz_row_col(r, cp_c * 16), bG + (size_t)r * K_DIM + kh + cp_c * 8);
        }
    };

    // ---- fragment loader for one k16 step ----
    auto load_frags = [&](uint32_t sA, uint32_t sB, int ks,
                          uint32_t a[4][4], uint32_t b[8][2]) {
        #pragma unroll
        for (int mt = 0; mt < 4; mt++) {
            const int row = wm * 64 + mt * 16 + rowA_in16;
            ldsm_x4(a[mt], sA + swz_row_col(row, ks * 32 + ksubA));
        }
        #pragma unroll
        for (int p = 0; p < 4; p++) {
            const int row = wn * 64 + p * 16 + rowB_in16;
            uint32_t r4[4];
            ldsm_x4(r4, sB + swz_row_col(row, ks * 32 + ksubB));
            b[2 * p][0] = r4[0]; b[2 * p][1] = r4[1];
            b[2 * p + 1][0] = r4[2]; b[2 * p + 1][1] = r4[3];
        }
    };

    // ---- prologue ----
    #pragma unroll
    for (int s = 0; s < STAGES - 1; s++) {
        load_stage_full(s, s);
        cp_commit();
    }
    cp_wait<STAGES - 2>();
    __syncthreads();

    // ---- main loop: rotating stage counters, interleaved loads, frag ping-pong ----
    int cstage = 0;                        // stage being consumed
    int lstage = STAGES - 1;               // stage being filled
    for (int kc = 0; kc < NCHUNK; kc++) {
        const int  kload  = kc + STAGES - 1;
        const bool doLoad = (kload < NCHUNK);
        const uint32_t lA = sb + lstage * STAGE_BYTES;
        const uint32_t lB = lA + A_STAGE_BYTES;
        const int  khl    = kload * BK;

        const uint32_t sA = sb + cstage * STAGE_BYTES;
        const uint32_t sB = sA + A_STAGE_BYTES;

        uint32_t afrag[2][4][4];
        uint32_t bfrag[2][8][2];
        load_frags(sA, sB, 0, afrag[0], bfrag[0]);

        #pragma unroll
        for (int ks = 0; ks < 4; ks++) {
            const int cur = ks & 1;
            // prefetch next k16 fragments before issuing MMAs
            if (ks < 3) load_frags(sA, sB, ks + 1, afrag[cur ^ 1], bfrag[cur ^ 1]);

            // interleave 4 cp.async (2 A-slices + 2 B-slices) for the prefetch chunk
            if (doLoad) {
                #pragma unroll
                for (int q = 0; q < 2; q++) {
                    int r = cp_r0 + (ks * 2 + q) * 16;
                    cp_async16(lA + swz_row_col(r, cp_c * 16),
                               aG + (size_t)r * K_DIM + khl + cp_c * 8);
                    cp_async16(lB + swz_row_col(r, cp_c * 16),
                               bG + (size_t)r * K_DIM + khl + cp_c * 8);
                }
            }

            #pragma unroll
            for (int mt = 0; mt < 4; mt++)
                #pragma unroll
                for (int nt = 0; nt < 8; nt++)
                    mma16816(acc[mt][nt], afrag[cur][mt], bfrag[cur][nt]);
        }
        cp_commit();

        cp_wait<STAGES - 2>();
        __syncthreads();

        if (++cstage == STAGES) cstage = 0;
        if (++lstage == STAGES) lstage = 0;
    }

    // ---- epilogue: scale * acc + bias, streaming (evict-first) float2 stores ----
    const int colbase = tile_n + wn * 64 + (lane & 3) * 2;
    float2 sc[8], bi[8];
    #pragma unroll
    for (int nt = 0; nt < 8; nt++) {
        sc[nt] = *reinterpret_cast<const float2*>(scale + colbase + nt * 8);
        bi[nt] = *reinterpret_cast<const float2*>(bias  + colbase + nt * 8);
    }

    #pragma unroll
    for (int mt = 0; mt < 4; mt++) {
        const int grow = tile_m + wm * 64 + mt * 16 + (lane >> 2);
        float* o0 = out + (size_t)grow * N_DIM + colbase;
        float* o1 = o0 + (size_t)8 * N_DIM;
        #pragma unroll
        for (int nt = 0; nt < 8; nt++) {
            stg_cs_f2(o0 + nt * 8,
                      acc[mt][nt][0] * sc[nt].x + bi[nt].x,
                      acc[mt][nt][1] * sc[nt].y + bi[nt].y);
            stg_cs_f2(o1 + nt * 8,
                      acc[mt][nt][2] * sc[nt].x + bi[nt].x,
                      acc[mt][nt][3] * sc[nt].y + bi[nt].y);
        }
    }
}

// ===================== launch =====================
extern "C" void kernel_launch(void* const* d_in, const int* in_sizes, int n_in,
                              void* d_out, int out_size) {
    const float* inp  = (const float*)d_in[0];   // (4, 2048, 4096) f32
    const int*   wgt  = (const int*)d_in[1];     // (16384, 4096) int32 (int8-valued)
    const float* wsc  = (const float*)d_in[2];   // (16384,) f32
    const float* bias = (const float*)d_in[3];   // (16384,) f32
    float* out = (float*)d_out;                  // (4, 2048, 16384) f32

    (void)in_sizes; (void)n_in; (void)out_size;

    cvt_kernel<<<CVT_A_BLOCKS + CVT_W_BLOCKS, 256>>>(
        reinterpret_cast<const float4*>(inp), reinterpret_cast<const int4*>(wgt));

    cudaFuncSetAttribute(gemm_f16_hmma,
                         cudaFuncAttributeMaxDynamicSharedMemorySize, SMEM_TOTAL);
    gemm_f16_hmma<<<TILES_M * TILES_N, THREADS, SMEM_TOTAL>>>(out, wsc, bias);
}

// round 12
// speedup vs baseline: 1.2625x; 1.0288x over previous
#include <cuda_runtime.h>
#include <cuda_fp16.h>
#include <cstdint>

// ===================== problem dims =====================
#define M_DIM 8192      // B*S = 4*2048
#define N_DIM 16384
#define K_DIM 4096

#define BM 128
#define BN 128
#define BK 64                         // halves per K-chunk (128 bytes per row)
#define NCHUNK (K_DIM / BK)           // 64
#define STAGES 3
#define THREADS 128                   // 4 warps, 64x64 warp tiles
#define TILES_M (M_DIM / BM)          // 64
#define TILES_N (N_DIM / BN)          // 128
#define GROUP_M 32                    // raster: m-tiles per group (2 exact passes over B)

// ===================== scratch (alloc-free) =====================
__device__ __half g_A[(size_t)M_DIM * K_DIM];   // 64 MB fp16 activations
__device__ __half g_B[(size_t)N_DIM * K_DIM];   // 128 MB fp16 weights (exact int8 values)

// ===================== PTX helpers (baseline features only) =====================
__device__ __forceinline__ uint32_t smem_to_u32(const void* p) {
    uint32_t a;
    asm("{ .reg .u64 t; cvta.to.shared.u64 t, %1; cvt.u32.u64 %0, t; }" : "=r"(a) : "l"(p));
    return a;
}
__device__ __forceinline__ void cp_async16(uint32_t dst, const void* src) {
    asm volatile("cp.async.cg.shared.global [%0], [%1], 16;" :: "r"(dst), "l"(src));
}
__device__ __forceinline__ void cp_commit() {
    asm volatile("cp.async.commit_group;" ::: "memory");
}
template <int N>
__device__ __forceinline__ void cp_wait() {
    asm volatile("cp.async.wait_group %0;" :: "n"(N) : "memory");
}
__device__ __forceinline__ void ldsm_x4(uint32_t* r, uint32_t addr) {
    asm volatile("ldmatrix.sync.aligned.m8n8.x4.shared.b16 {%0,%1,%2,%3}, [%4];"
                 : "=r"(r[0]), "=r"(r[1]), "=r"(r[2]), "=r"(r[3]) : "r"(addr));
}
__device__ __forceinline__ void mma16816(float* d, const uint32_t* a, const uint32_t* b) {
    asm volatile(
        "mma.sync.aligned.m16n8k16.row.col.f32.f16.f16.f32 "
        "{%0,%1,%2,%3}, {%4,%5,%6,%7}, {%8,%9}, {%0,%1,%2,%3};"
        : "+f"(d[0]), "+f"(d[1]), "+f"(d[2]), "+f"(d[3])
        : "r"(a[0]), "r"(a[1]), "r"(a[2]), "r"(a[3]), "r"(b[0]), "r"(b[1]));
}
// streaming (evict-first) float2 store — keeps B stripe resident in L2
__device__ __forceinline__ void stg_cs_f2(float* p, float x, float y) {
    asm volatile("st.global.cs.v2.f32 [%0], {%1, %2};" :: "l"(p), "f"(x), "f"(y) : "memory");
}

// SW128 swizzle for 128B rows: 16B chunk index ^= (row & 7)
__device__ __forceinline__ uint32_t swz_row_col(int row, int colbytes) {
    return (uint32_t)(row * 128) + (uint32_t)(colbytes ^ ((row & 7) << 4));
}

// ===================== SMEM layout =====================
#define A_STAGE_BYTES (BM * 128)              // 16384
#define B_STAGE_BYTES (BN * 128)              // 16384
#define STAGE_BYTES   (A_STAGE_BYTES + B_STAGE_BYTES)   // 32768
#define SMEM_BODY     (STAGES * STAGE_BYTES)  // 98304
#define SMEM_TOTAL    (SMEM_BODY + 128)       // manual 128B alignment headroom

// ===================== fused conversion kernel =====================
struct alignas(16) H8 { __half2 a, b, c, d; };

#define CVT_A_BLOCKS 16384
#define CVT_W_BLOCKS 32768

__global__ void cvt_kernel(const float4* __restrict__ inA, const int4* __restrict__ inW) {
    if (blockIdx.x < CVT_A_BLOCKS) {
        size_t i = (size_t)blockIdx.x * blockDim.x + threadIdx.x;
        float4 v0 = inA[2 * i];
        float4 v1 = inA[2 * i + 1];
        H8 h;
        h.a = __floats2half2_rn(v0.x, v0.y);
        h.b = __floats2half2_rn(v0.z, v0.w);
        h.c = __floats2half2_rn(v1.x, v1.y);
        h.d = __floats2half2_rn(v1.z, v1.w);
        reinterpret_cast<H8*>(g_A)[i] = h;
    } else {
        size_t i = (size_t)(blockIdx.x - CVT_A_BLOCKS) * blockDim.x + threadIdx.x;
        int4 v0 = inW[2 * i];
        int4 v1 = inW[2 * i + 1];
        H8 h;
        h.a = __floats2half2_rn((float)v0.x, (float)v0.y);
        h.b = __floats2half2_rn((float)v0.z, (float)v0.w);
        h.c = __floats2half2_rn((float)v1.x, (float)v1.y);
        h.d = __floats2half2_rn((float)v1.z, (float)v1.w);
        reinterpret_cast<H8*>(g_B)[i] = h;
    }
}

// ===================== GEMM kernel (cross-chunk fragment pipelining) =====================
__global__ void __launch_bounds__(THREADS, 2)
gemm_f16_hmma(float* __restrict__ out,
              const float* __restrict__ scale,
              const float* __restrict__ bias) {
    extern __shared__ char smem_raw[];
    char* smem = (char*)(((uintptr_t)smem_raw + 127) & ~(uintptr_t)127);
    const uint32_t sb = smem_to_u32(smem);

    const int tid  = threadIdx.x;
    const int wid  = tid >> 5;
    const int lane = tid & 31;
    const int wm   = wid >> 1;   // 0..1  (m-warp, 64 rows)
    const int wn   = wid & 1;    // 0..1  (n-warp, 64 cols)

    // ---- CTA raster swizzle: m fastest within groups of GROUP_M m-tiles ----
    const int bid       = blockIdx.x;
    const int per_group = GROUP_M * TILES_N;           // 4096
    const int g         = bid / per_group;
    const int r_        = bid % per_group;
    const int tile_m    = (g * GROUP_M + (r_ % GROUP_M)) * BM;
    const int tile_n    = (r_ / GROUP_M) * BN;

    const __half* aG = g_A + (size_t)tile_m * K_DIM;
    const __half* bG = g_B + (size_t)tile_n * K_DIM;

    // ldmatrix per-lane row/col-sub mappings (validated round-2/5 logic)
    const int rowA_in16 = ((lane >> 3) & 1) * 8 + (lane & 7);
    const int ksubA     = ((lane >> 4) & 1) * 16;
    const int rowB_in16 = ((lane >> 4) & 1) * 8 + (lane & 7);
    const int ksubB     = ((lane >> 3) & 1) * 16;

    // per-thread cp.async coordinates (idx = tid + j*128 ; r = idx>>3, c = idx&7)
    const int cp_r0 = tid >> 3;            // rows advance by 16 per j
    const int cp_c  = tid & 7;

    float acc[4][8][4];
    #pragma unroll
    for (int mt = 0; mt < 4; mt++)
        #pragma unroll
        for (int nt = 0; nt < 8; nt++)
            #pragma unroll
            for (int q = 0; q < 4; q++) acc[mt][nt][q] = 0.0f;

    // ---- full-chunk producer (prologue only) ----
    auto load_stage_full = [&](int stage, int kc) {
        const uint32_t sA = sb + stage * STAGE_BYTES;
        const uint32_t sB = sA + A_STAGE_BYTES;
        const int kh = kc * BK;
        #pragma unroll
        for (int j = 0; j < 8; j++) {
            int r = cp_r0 + j * 16;
            cp_async16(sA + swz_row_col(r, cp_c * 16), aG + (size_t)r * K_DIM + kh + cp_c * 8);
        }
        #pragma unroll
        for (int j = 0; j < 8; j++) {
            int r = cp_r0 + j * 16;
            cp_async16(sB + swz_row_col(r, cp_c * 16), bG + (size_t)r * K_DIM + kh + cp_c * 8);
        }
    };

    // ---- fragment loader for one k16 step ----
    auto load_frags = [&](uint32_t sA, uint32_t sB, int ks,
                          uint32_t a[4][4], uint32_t b[8][2]) {
        #pragma unroll
        for (int mt = 0; mt < 4; mt++) {
            const int row = wm * 64 + mt * 16 + rowA_in16;
            ldsm_x4(a[mt], sA + swz_row_col(row, ks * 32 + ksubA));
        }
        #pragma unroll
        for (int p = 0; p < 4; p++) {
            const int row = wn * 64 + p * 16 + rowB_in16;
            uint32_t r4[4];
            ldsm_x4(r4, sB + swz_row_col(row, ks * 32 + ksubB));
            b[2 * p][0] = r4[0]; b[2 * p][1] = r4[1];
            b[2 * p + 1][0] = r4[2]; b[2 * p + 1][1] = r4[3];
        }
    };

    // ---- prologue: fill 2 stages, then preload chunk-0 ks=0 fragments ----
    #pragma unroll
    for (int s = 0; s < STAGES - 1; s++) {
        load_stage_full(s, s);
        cp_commit();
    }
    cp_wait<STAGES - 2>();
    __syncthreads();

    uint32_t afrag[2][4][4];
    uint32_t bfrag[2][8][2];
    load_frags(sb, sb + A_STAGE_BYTES, 0, afrag[0], bfrag[0]);
    int buf = 0;

    // ---- main loop: barrier inside ks=3; next chunk's ks=0 frags prefetched
    //      under the last 32 MMAs of the current chunk ----
    int cstage = 0;                        // stage being consumed
    int lstage = STAGES - 1;               // stage being filled
    for (int kc = 0; kc < NCHUNK; kc++) {
        const int  kload  = kc + STAGES - 1;
        const bool doLoad = (kload < NCHUNK);
        const uint32_t lA = sb + lstage * STAGE_BYTES;
        const uint32_t lB = lA + A_STAGE_BYTES;
        const int  khl    = kload * BK;

        const uint32_t sA = sb + cstage * STAGE_BYTES;
        const uint32_t sB = sA + A_STAGE_BYTES;

        const int nstage = (cstage + 1 == STAGES) ? 0 : cstage + 1;
        const uint32_t nA = sb + nstage * STAGE_BYTES;
        const uint32_t nB = nA + A_STAGE_BYTES;

        #pragma unroll
        for (int ks = 0; ks < 4; ks++) {
            // interleave 4 cp.async (2 A-slices + 2 B-slices) for the prefetch chunk
            if (doLoad) {
                #pragma unroll
                for (int q = 0; q < 2; q++) {
                    int r = cp_r0 + (ks * 2 + q) * 16;
                    cp_async16(lA + swz_row_col(r, cp_c * 16),
                               aG + (size_t)r * K_DIM + khl + cp_c * 8);
                    cp_async16(lB + swz_row_col(r, cp_c * 16),
                               bG + (size_t)r * K_DIM + khl + cp_c * 8);
                }
            }

            if (ks < 3) {
                // prefetch next k16 fragments of the current chunk
                load_frags(sA, sB, ks + 1, afrag[buf ^ 1], bfrag[buf ^ 1]);
            } else {
                // chunk boundary: commit, wait, barrier, then prefetch next
                // chunk's ks=0 fragments (stage nstage is complete after wait<1>)
                cp_commit();
                cp_wait<STAGES - 2>();
                __syncthreads();
                if (kc < NCHUNK - 1)
                    load_frags(nA, nB, 0, afrag[buf ^ 1], bfrag[buf ^ 1]);
            }

            #pragma unroll
            for (int mt = 0; mt < 4; mt++)
                #pragma unroll
                for (int nt = 0; nt < 8; nt++)
                    mma16816(acc[mt][nt], afrag[buf][mt], bfrag[buf][nt]);
            buf ^= 1;
        }

        cstage = nstage;
        if (++lstage == STAGES) lstage = 0;
    }

    // ---- epilogue: scale * acc + bias, streaming (evict-first) float2 stores ----
    const int colbase = tile_n + wn * 64 + (lane & 3) * 2;
    float2 sc[8], bi[8];
    #pragma unroll
    for (int nt = 0; nt < 8; nt++) {
        sc[nt] = *reinterpret_cast<const float2*>(scale + colbase + nt * 8);
        bi[nt] = *reinterpret_cast<const float2*>(bias  + colbase + nt * 8);
    }

    #pragma unroll
    for (int mt = 0; mt < 4; mt++) {
        const int grow = tile_m + wm * 64 + mt * 16 + (lane >> 2);
        float* o0 = out + (size_t)grow * N_DIM + colbase;
        float* o1 = o0 + (size_t)8 * N_DIM;
        #pragma unroll
        for (int nt = 0; nt < 8; nt++) {
            stg_cs_f2(o0 + nt * 8,
                      acc[mt][nt][0] * sc[nt].x + bi[nt].x,
                      acc[mt][nt][1] * sc[nt].y + bi[nt].y);
            stg_cs_f2(o1 + nt * 8,
                      acc[mt][nt][2] * sc[nt].x + bi[nt].x,
                      acc[mt][nt][3] * sc[nt].y + bi[nt].y);
        }
    }
}

// ===================== launch =====================
extern "C" void kernel_launch(void* const* d_in, const int* in_sizes, int n_in,
                              void* d_out, int out_size) {
    const float* inp  = (const float*)d_in[0];   // (4, 2048, 4096) f32
    const int*   wgt  = (const int*)d_in[1];     // (16384, 4096) int32 (int8-valued)
    const float* wsc  = (const float*)d_in[2];   // (16384,) f32
    const float* bias = (const float*)d_in[3];   // (16384,) f32
    float* out = (float*)d_out;                  // (4, 2048, 16384) f32

    (void)in_sizes; (void)n_in; (void)out_size;

    cvt_kernel<<<CVT_A_BLOCKS + CVT_W_BLOCKS, 256>>>(
        reinterpret_cast<const float4*>(inp), reinterpret_cast<const int4*>(wgt));

    cudaFuncSetAttribute(gemm_f16_hmma,
                         cudaFuncAttributeMaxDynamicSharedMemorySize, SMEM_TOTAL);
    gemm_f16_hmma<<<TILES_M * TILES_N, THREADS, SMEM_TOTAL>>>(out, wsc, bias);
}

// round 13
// speedup vs baseline: 1.2858x; 1.0185x over previous
#include <cuda_runtime.h>
#include <cuda_fp16.h>
#include <cstdint>
#include <type_traits>

// ===================== problem dims =====================
#define M_DIM 8192      // B*S = 4*2048
#define N_DIM 16384
#define K_DIM 4096

#define BM 128
#define BN 128
#define BK 64                         // halves per K-chunk (128 bytes per row)
#define NCHUNK (K_DIM / BK)           // 64
#define STAGES 3
#define THREADS 128                   // 4 warps, 64x64 warp tiles
#define TILES_M (M_DIM / BM)          // 64
#define TILES_N (N_DIM / BN)          // 128
#define GROUP_M 32                    // raster: m-tiles per group (2 exact passes over B)

// ===================== scratch (alloc-free) =====================
__device__ __half g_A[(size_t)M_DIM * K_DIM];   // 64 MB fp16 activations
__device__ __half g_B[(size_t)N_DIM * K_DIM];   // 128 MB fp16 weights (exact int8 values)

// ===================== PTX helpers (baseline features only) =====================
__device__ __forceinline__ uint32_t smem_to_u32(const void* p) {
    uint32_t a;
    asm("{ .reg .u64 t; cvta.to.shared.u64 t, %1; cvt.u32.u64 %0, t; }" : "=r"(a) : "l"(p));
    return a;
}
__device__ __forceinline__ void cp_async16(uint32_t dst, const void* src) {
    asm volatile("cp.async.cg.shared.global [%0], [%1], 16;" :: "r"(dst), "l"(src));
}
__device__ __forceinline__ void cp_commit() {
    asm volatile("cp.async.commit_group;" ::: "memory");
}
template <int N>
__device__ __forceinline__ void cp_wait() {
    asm volatile("cp.async.wait_group %0;" :: "n"(N) : "memory");
}
__device__ __forceinline__ void ldsm_x4(uint32_t* r, uint32_t addr) {
    asm volatile("ldmatrix.sync.aligned.m8n8.x4.shared.b16 {%0,%1,%2,%3}, [%4];"
                 : "=r"(r[0]), "=r"(r[1]), "=r"(r[2]), "=r"(r[3]) : "r"(addr));
}
__device__ __forceinline__ void mma16816(float* d, const uint32_t* a, const uint32_t* b) {
    asm volatile(
        "mma.sync.aligned.m16n8k16.row.col.f32.f16.f16.f32 "
        "{%0,%1,%2,%3}, {%4,%5,%6,%7}, {%8,%9}, {%0,%1,%2,%3};"
        : "+f"(d[0]), "+f"(d[1]), "+f"(d[2]), "+f"(d[3])
        : "r"(a[0]), "r"(a[1]), "r"(a[2]), "r"(a[3]), "r"(b[0]), "r"(b[1]));
}
// streaming (evict-first) float2 store — keeps B stripe resident in L2
__device__ __forceinline__ void stg_cs_f2(float* p, float x, float y) {
    asm volatile("st.global.cs.v2.f32 [%0], {%1, %2};" :: "l"(p), "f"(x), "f"(y) : "memory");
}

// SW128 swizzle for 128B rows: 16B chunk index ^= (row & 7)
__device__ __forceinline__ uint32_t swz_row_col(int row, int colbytes) {
    return (uint32_t)(row * 128) + (uint32_t)(colbytes ^ ((row & 7) << 4));
}

// ===================== SMEM layout =====================
#define A_STAGE_BYTES (BM * 128)              // 16384
#define B_STAGE_BYTES (BN * 128)              // 16384
#define STAGE_BYTES   (A_STAGE_BYTES + B_STAGE_BYTES)   // 32768
#define SMEM_BODY     (STAGES * STAGE_BYTES)  // 98304
#define SMEM_TOTAL    (SMEM_BODY + 128)       // manual 128B alignment headroom

// ===================== fused conversion kernel =====================
struct alignas(16) H8 { __half2 a, b, c, d; };

#define CVT_A_BLOCKS 16384
#define CVT_W_BLOCKS 32768

__global__ void cvt_kernel(const float4* __restrict__ inA, const int4* __restrict__ inW) {
    if (blockIdx.x < CVT_A_BLOCKS) {
        size_t i = (size_t)blockIdx.x * blockDim.x + threadIdx.x;
        float4 v0 = inA[2 * i];
        float4 v1 = inA[2 * i + 1];
        H8 h;
        h.a = __floats2half2_rn(v0.x, v0.y);
        h.b = __floats2half2_rn(v0.z, v0.w);
        h.c = __floats2half2_rn(v1.x, v1.y);
        h.d = __floats2half2_rn(v1.z, v1.w);
        reinterpret_cast<H8*>(g_A)[i] = h;
    } else {
        size_t i = (size_t)(blockIdx.x - CVT_A_BLOCKS) * blockDim.x + threadIdx.x;
        int4 v0 = inW[2 * i];
        int4 v1 = inW[2 * i + 1];
        H8 h;
        h.a = __floats2half2_rn((float)v0.x, (float)v0.y);
        h.b = __floats2half2_rn((float)v0.z, (float)v0.w);
        h.c = __floats2half2_rn((float)v1.x, (float)v1.y);
        h.d = __floats2half2_rn((float)v1.z, (float)v1.w);
        reinterpret_cast<H8*>(g_B)[i] = h;
    }
}

// ===================== GEMM kernel (compile-time stage specialization) =====================
__global__ void __launch_bounds__(THREADS, 2)
gemm_f16_hmma(float* __restrict__ out,
              const float* __restrict__ scale,
              const float* __restrict__ bias) {
    extern __shared__ char smem_raw[];
    char* smem = (char*)(((uintptr_t)smem_raw + 127) & ~(uintptr_t)127);
    const uint32_t sb = smem_to_u32(smem);

    const int tid  = threadIdx.x;
    const int wid  = tid >> 5;
    const int lane = tid & 31;
    const int wm   = wid >> 1;   // 0..1  (m-warp, 64 rows)
    const int wn   = wid & 1;    // 0..1  (n-warp, 64 cols)

    // ---- CTA raster swizzle: m fastest within groups of GROUP_M m-tiles ----
    const int bid       = blockIdx.x;
    const int per_group = GROUP_M * TILES_N;           // 4096
    const int g         = bid / per_group;
    const int r_        = bid % per_group;
    const int tile_m    = (g * GROUP_M + (r_ % GROUP_M)) * BM;
    const int tile_n    = (r_ / GROUP_M) * BN;

    const __half* aG = g_A + (size_t)tile_m * K_DIM;
    const __half* bG = g_B + (size_t)tile_n * K_DIM;

    // ldmatrix per-lane row/col-sub mappings (validated round-2/5 logic)
    const int rowA_in16 = ((lane >> 3) & 1) * 8 + (lane & 7);
    const int ksubA     = ((lane >> 4) & 1) * 16;
    const int rowB_in16 = ((lane >> 4) & 1) * 8 + (lane & 7);
    const int ksubB     = ((lane >> 3) & 1) * 16;

    // per-thread cp.async coordinates (idx = tid + j*128 ; r = idx>>3, c = idx&7)
    const int cp_r0 = tid >> 3;            // rows advance by 16 per j
    const int cp_c  = tid & 7;

    float acc[4][8][4];
    #pragma unroll
    for (int mt = 0; mt < 4; mt++)
        #pragma unroll
        for (int nt = 0; nt < 8; nt++)
            #pragma unroll
            for (int q = 0; q < 4; q++) acc[mt][nt][q] = 0.0f;

    // ---- full-chunk producer (prologue only) ----
    auto load_stage_full = [&](int stage, int kc) {
        const uint32_t sA = sb + stage * STAGE_BYTES;
        const uint32_t sB = sA + A_STAGE_BYTES;
        const int kh = kc * BK;
        #pragma unroll
        for (int j = 0; j < 8; j++) {
            int r = cp_r0 + j * 16;
            cp_async16(sA + swz_row_col(r, cp_c * 16), aG + (size_t)r * K_DIM + kh + cp_c * 8);
        }
        #pragma unroll
        for (int j = 0; j < 8; j++) {
            int r = cp_r0 + j * 16;
            cp_async16(sB + swz_row_col(r, cp_c * 16), bG + (size_t)r * K_DIM + kh + cp_c * 8);
        }
    };

    // ---- fragment loader for one k16 step ----
    auto load_frags = [&](uint32_t sA, uint32_t sB, int ks,
                          uint32_t a[4][4], uint32_t b[8][2]) {
        #pragma unroll
        for (int mt = 0; mt < 4; mt++) {
            const int row = wm * 64 + mt * 16 + rowA_in16;
            ldsm_x4(a[mt], sA + swz_row_col(row, ks * 32 + ksubA));
        }
        #pragma unroll
        for (int p = 0; p < 4; p++) {
            const int row = wn * 64 + p * 16 + rowB_in16;
            uint32_t r4[4];
            ldsm_x4(r4, sB + swz_row_col(row, ks * 32 + ksubB));
            b[2 * p][0] = r4[0]; b[2 * p][1] = r4[1];
            b[2 * p + 1][0] = r4[2]; b[2 * p + 1][1] = r4[3];
        }
    };

    // ---- prologue: fill 2 stages, then preload chunk-0 ks=0 fragments ----
    #pragma unroll
    for (int s = 0; s < STAGES - 1; s++) {
        load_stage_full(s, s);
        cp_commit();
    }
    cp_wait<STAGES - 2>();
    __syncthreads();

    uint32_t afrag[2][4][4];
    uint32_t bfrag[2][8][2];
    load_frags(sb, sb + A_STAGE_BYTES, 0, afrag[0], bfrag[0]);

    int kc = 0;   // advanced inside chunk_body

    // ---- one K-chunk with COMPILE-TIME stage indices ----
    auto chunk_body = [&](auto CSTc, auto LSTc) {
        constexpr int CST = CSTc.value;                    // stage consumed
        constexpr int LST = LSTc.value;                    // stage filled
        constexpr int NST = (CST + 1) % STAGES;            // next consumed stage

        const int  kload  = kc + STAGES - 1;
        const bool doLoad = (kload < NCHUNK);
        const int  khl    = kload * BK;

        const uint32_t lA = sb + LST * STAGE_BYTES;
        const uint32_t lB = lA + A_STAGE_BYTES;
        const uint32_t sA = sb + CST * STAGE_BYTES;
        const uint32_t sB = sA + A_STAGE_BYTES;
        const uint32_t nA = sb + NST * STAGE_BYTES;
        const uint32_t nB = nA + A_STAGE_BYTES;

        #pragma unroll
        for (int ks = 0; ks < 4; ks++) {
            const int cur = ks & 1;   // compile-time under unroll
            // interleave 4 cp.async (2 A-slices + 2 B-slices) for the prefetch chunk
            if (doLoad) {
                #pragma unroll
                for (int q = 0; q < 2; q++) {
                    int r = cp_r0 + (ks * 2 + q) * 16;
                    cp_async16(lA + swz_row_col(r, cp_c * 16),
                               aG + (size_t)r * K_DIM + khl + cp_c * 8);
                    cp_async16(lB + swz_row_col(r, cp_c * 16),
                               bG + (size_t)r * K_DIM + khl + cp_c * 8);
                }
            }

            if (ks < 3) {
                // prefetch next k16 fragments of the current chunk
                load_frags(sA, sB, ks + 1, afrag[cur ^ 1], bfrag[cur ^ 1]);
            } else {
                // chunk boundary: commit, wait, barrier, then prefetch next
                // chunk's ks=0 fragments (stage NST complete after wait<1>)
                cp_commit();
                cp_wait<STAGES - 2>();
                __syncthreads();
                if (kc < NCHUNK - 1)
                    load_frags(nA, nB, 0, afrag[cur ^ 1], bfrag[cur ^ 1]);
            }

            #pragma unroll
            for (int mt = 0; mt < 4; mt++)
                #pragma unroll
                for (int nt = 0; nt < 8; nt++)
                    mma16816(acc[mt][nt], afrag[cur][mt], bfrag[cur][nt]);
        }
        kc++;
    };

    using I0 = std::integral_constant<int, 0>;
    using I1 = std::integral_constant<int, 1>;
    using I2 = std::integral_constant<int, 2>;

    // 21 iterations x 3 chunks = 63, plus chunk 63 (cstage pattern: 0,1,2 repeating)
    #pragma unroll 1
    for (int it = 0; it < NCHUNK / 3; it++) {      // 21
        chunk_body(I0{}, I2{});
        chunk_body(I1{}, I0{});
        chunk_body(I2{}, I1{});
    }
    chunk_body(I0{}, I2{});                        // chunk 63

    // ---- epilogue: scale * acc + bias, streaming (evict-first) float2 stores ----
    const int colbase = tile_n + wn * 64 + (lane & 3) * 2;
    float2 sc[8], bi[8];
    #pragma unroll
    for (int nt = 0; nt < 8; nt++) {
        sc[nt] = *reinterpret_cast<const float2*>(scale + colbase + nt * 8);
        bi[nt] = *reinterpret_cast<const float2*>(bias  + colbase + nt * 8);
    }

    #pragma unroll
    for (int mt = 0; mt < 4; mt++) {
        const int grow = tile_m + wm * 64 + mt * 16 + (lane >> 2);
        float* o0 = out + (size_t)grow * N_DIM + colbase;
        float* o1 = o0 + (size_t)8 * N_DIM;
        #pragma unroll
        for (int nt = 0; nt < 8; nt++) {
            stg_cs_f2(o0 + nt * 8,
                      acc[mt][nt][0] * sc[nt].x + bi[nt].x,
                      acc[mt][nt][1] * sc[nt].y + bi[nt].y);
            stg_cs_f2(o1 + nt * 8,
                      acc[mt][nt][2] * sc[nt].x + bi[nt].x,
                      acc[mt][nt][3] * sc[nt].y + bi[nt].y);
        }
    }
}

// ===================== launch =====================
extern "C" void kernel_launch(void* const* d_in, const int* in_sizes, int n_in,
                              void* d_out, int out_size) {
    const float* inp  = (const float*)d_in[0];   // (4, 2048, 4096) f32
    const int*   wgt  = (const int*)d_in[1];     // (16384, 4096) int32 (int8-valued)
    const float* wsc  = (const float*)d_in[2];   // (16384,) f32
    const float* bias = (const float*)d_in[3];   // (16384,) f32
    float* out = (float*)d_out;                  // (4, 2048, 16384) f32

    (void)in_sizes; (void)n_in; (void)out_size;

    cvt_kernel<<<CVT_A_BLOCKS + CVT_W_BLOCKS, 256>>>(
        reinterpret_cast<const float4*>(inp), reinterpret_cast<const int4*>(wgt));

    cudaFuncSetAttribute(gemm_f16_hmma,
                         cudaFuncAttributeMaxDynamicSharedMemorySize, SMEM_TOTAL);
    gemm_f16_hmma<<<TILES_M * TILES_N, THREADS, SMEM_TOTAL>>>(out, wsc, bias);
}

// round 14
// speedup vs baseline: 1.2859x; 1.0000x over previous
#include <cuda_runtime.h>
#include <cuda_fp16.h>
#include <cstdint>
#include <type_traits>

// ===================== problem dims =====================
#define M_DIM 8192      // B*S = 4*2048
#define N_DIM 16384
#define K_DIM 4096

#define BM 128
#define BN 128
#define BK 64                         // halves per K-chunk (128 bytes per row)
#define NCHUNK (K_DIM / BK)           // 64
#define STAGES 3
#define THREADS 128                   // 4 warps, 64x64 warp tiles
#define TILES_M (M_DIM / BM)          // 64
#define TILES_N (N_DIM / BN)          // 128
#define GROUP_M 32                    // raster: m-tiles per group (2 exact passes over B)

// ===================== scratch (alloc-free) =====================
__device__ __half g_A[(size_t)M_DIM * K_DIM];   // 64 MB fp16 activations
__device__ __half g_B[(size_t)N_DIM * K_DIM];   // 128 MB fp16 weights (exact int8 values)

// ===================== PTX helpers (baseline features only) =====================
__device__ __forceinline__ uint32_t smem_to_u32(const void* p) {
    uint32_t a;
    asm("{ .reg .u64 t; cvta.to.shared.u64 t, %1; cvt.u32.u64 %0, t; }" : "=r"(a) : "l"(p));
    return a;
}
__device__ __forceinline__ void cp_async16(uint32_t dst, const void* src) {
    asm volatile("cp.async.cg.shared.global [%0], [%1], 16;" :: "r"(dst), "l"(src));
}
__device__ __forceinline__ void cp_commit() {
    asm volatile("cp.async.commit_group;" ::: "memory");
}
template <int N>
__device__ __forceinline__ void cp_wait() {
    asm volatile("cp.async.wait_group %0;" :: "n"(N) : "memory");
}
__device__ __forceinline__ void ldsm_x4(uint32_t* r, uint32_t addr) {
    asm volatile("ldmatrix.sync.aligned.m8n8.x4.shared.b16 {%0,%1,%2,%3}, [%4];"
                 : "=r"(r[0]), "=r"(r[1]), "=r"(r[2]), "=r"(r[3]) : "r"(addr));
}
__device__ __forceinline__ void mma16816(float* d, const uint32_t* a, const uint32_t* b) {
    asm volatile(
        "mma.sync.aligned.m16n8k16.row.col.f32.f16.f16.f32 "
        "{%0,%1,%2,%3}, {%4,%5,%6,%7}, {%8,%9}, {%0,%1,%2,%3};"
        : "+f"(d[0]), "+f"(d[1]), "+f"(d[2]), "+f"(d[3])
        : "r"(a[0]), "r"(a[1]), "r"(a[2]), "r"(a[3]), "r"(b[0]), "r"(b[1]));
}
// streaming (evict-first) float2 store — keeps B stripe resident in L2
__device__ __forceinline__ void stg_cs_f2(float* p, float x, float y) {
    asm volatile("st.global.cs.v2.f32 [%0], {%1, %2};" :: "l"(p), "f"(x), "f"(y) : "memory");
}
// streaming 16B load / store for the conversion kernel
__device__ __forceinline__ uint4 ldg_cs_16(const void* p) {
    uint4 v;
    asm volatile("ld.global.cs.v4.b32 {%0,%1,%2,%3}, [%4];"
                 : "=r"(v.x), "=r"(v.y), "=r"(v.z), "=r"(v.w) : "l"(p));
    return v;
}
__device__ __forceinline__ void stg_cs_16(void* p, uint4 v) {
    asm volatile("st.global.cs.v4.b32 [%0], {%1,%2,%3,%4};"
                 :: "l"(p), "r"(v.x), "r"(v.y), "r"(v.z), "r"(v.w) : "memory");
}

// SW128 swizzle for 128B rows: 16B chunk index ^= (row & 7)
__device__ __forceinline__ uint32_t swz_row_col(int row, int colbytes) {
    return (uint32_t)(row * 128) + (uint32_t)(colbytes ^ ((row & 7) << 4));
}

// ===================== SMEM layout =====================
#define A_STAGE_BYTES (BM * 128)              // 16384
#define B_STAGE_BYTES (BN * 128)              // 16384
#define STAGE_BYTES   (A_STAGE_BYTES + B_STAGE_BYTES)   // 32768
#define SMEM_BODY     (STAGES * STAGE_BYTES)  // 98304
#define SMEM_TOTAL    (SMEM_BODY + 128)       // manual 128B alignment headroom

// ===================== fused conversion kernel (streaming) =====================
#define CVT_A_BLOCKS 16384
#define CVT_W_BLOCKS 32768

__device__ __forceinline__ uint32_t h2_u32(__half2 h) {
    uint32_t u; *reinterpret_cast<__half2*>(&u) = h; return u;
}

__global__ void cvt_kernel(const float4* __restrict__ inA, const int4* __restrict__ inW) {
    if (blockIdx.x < CVT_A_BLOCKS) {
        size_t i = (size_t)blockIdx.x * blockDim.x + threadIdx.x;
        uint4 r0 = ldg_cs_16(inA + 2 * i);
        uint4 r1 = ldg_cs_16(inA + 2 * i + 1);
        float4 v0 = *reinterpret_cast<float4*>(&r0);
        float4 v1 = *reinterpret_cast<float4*>(&r1);
        uint4 o;
        o.x = h2_u32(__floats2half2_rn(v0.x, v0.y));
        o.y = h2_u32(__floats2half2_rn(v0.z, v0.w));
        o.z = h2_u32(__floats2half2_rn(v1.x, v1.y));
        o.w = h2_u32(__floats2half2_rn(v1.z, v1.w));
        stg_cs_16(reinterpret_cast<uint4*>(g_A) + i, o);
    } else {
        size_t i = (size_t)(blockIdx.x - CVT_A_BLOCKS) * blockDim.x + threadIdx.x;
        uint4 r0 = ldg_cs_16(inW + 2 * i);
        uint4 r1 = ldg_cs_16(inW + 2 * i + 1);
        int4 v0 = *reinterpret_cast<int4*>(&r0);
        int4 v1 = *reinterpret_cast<int4*>(&r1);
        uint4 o;
        o.x = h2_u32(__floats2half2_rn((float)v0.x, (float)v0.y));
        o.y = h2_u32(__floats2half2_rn((float)v0.z, (float)v0.w));
        o.z = h2_u32(__floats2half2_rn((float)v1.x, (float)v1.y));
        o.w = h2_u32(__floats2half2_rn((float)v1.z, (float)v1.w));
        stg_cs_16(reinterpret_cast<uint4*>(g_B) + i, o);
    }
}

// ===================== GEMM kernel (fully specialized chunk variants) =====================
__global__ void __launch_bounds__(THREADS, 2)
gemm_f16_hmma(float* __restrict__ out,
              const float* __restrict__ scale,
              const float* __restrict__ bias) {
    extern __shared__ char smem_raw[];
    char* smem = (char*)(((uintptr_t)smem_raw + 127) & ~(uintptr_t)127);
    const uint32_t sb = smem_to_u32(smem);

    const int tid  = threadIdx.x;
    const int wid  = tid >> 5;
    const int lane = tid & 31;
    const int wm   = wid >> 1;   // 0..1  (m-warp, 64 rows)
    const int wn   = wid & 1;    // 0..1  (n-warp, 64 cols)

    // ---- CTA raster swizzle: m fastest within groups of GROUP_M m-tiles ----
    const int bid       = blockIdx.x;
    const int per_group = GROUP_M * TILES_N;           // 4096
    const int g         = bid / per_group;
    const int r_        = bid % per_group;
    const int tile_m    = (g * GROUP_M + (r_ % GROUP_M)) * BM;
    const int tile_n    = (r_ / GROUP_M) * BN;

    const __half* aG = g_A + (size_t)tile_m * K_DIM;
    const __half* bG = g_B + (size_t)tile_n * K_DIM;

    // ldmatrix per-lane row/col-sub mappings (validated round-2/5 logic)
    const int rowA_in16 = ((lane >> 3) & 1) * 8 + (lane & 7);
    const int ksubA     = ((lane >> 4) & 1) * 16;
    const int rowB_in16 = ((lane >> 4) & 1) * 8 + (lane & 7);
    const int ksubB     = ((lane >> 3) & 1) * 16;

    // per-thread cp.async coordinates (idx = tid + j*128 ; r = idx>>3, c = idx&7)
    const int cp_r0 = tid >> 3;            // rows advance by 16 per j
    const int cp_c  = tid & 7;

    float acc[4][8][4];
    #pragma unroll
    for (int mt = 0; mt < 4; mt++)
        #pragma unroll
        for (int nt = 0; nt < 8; nt++)
            #pragma unroll
            for (int q = 0; q < 4; q++) acc[mt][nt][q] = 0.0f;

    // ---- full-chunk producer (prologue only) ----
    auto load_stage_full = [&](int stage, int kc) {
        const uint32_t sA = sb + stage * STAGE_BYTES;
        const uint32_t sB = sA + A_STAGE_BYTES;
        const int kh = kc * BK;
        #pragma unroll
        for (int j = 0; j < 8; j++) {
            int r = cp_r0 + j * 16;
            cp_async16(sA + swz_row_col(r, cp_c * 16), aG + (size_t)r * K_DIM + kh + cp_c * 8);
        }
        #pragma unroll
        for (int j = 0; j < 8; j++) {
            int r = cp_r0 + j * 16;
            cp_async16(sB + swz_row_col(r, cp_c * 16), bG + (size_t)r * K_DIM + kh + cp_c * 8);
        }
    };

    // ---- fragment loader for one k16 step ----
    auto load_frags = [&](uint32_t sA, uint32_t sB, int ks,
                          uint32_t a[4][4], uint32_t b[8][2]) {
        #pragma unroll
        for (int mt = 0; mt < 4; mt++) {
            const int row = wm * 64 + mt * 16 + rowA_in16;
            ldsm_x4(a[mt], sA + swz_row_col(row, ks * 32 + ksubA));
        }
        #pragma unroll
        for (int p = 0; p < 4; p++) {
            const int row = wn * 64 + p * 16 + rowB_in16;
            uint32_t r4[4];
            ldsm_x4(r4, sB + swz_row_col(row, ks * 32 + ksubB));
            b[2 * p][0] = r4[0]; b[2 * p][1] = r4[1];
            b[2 * p + 1][0] = r4[2]; b[2 * p + 1][1] = r4[3];
        }
    };

    // ---- prologue: fill 2 stages, then preload chunk-0 ks=0 fragments ----
    #pragma unroll
    for (int s = 0; s < STAGES - 1; s++) {
        load_stage_full(s, s);
        cp_commit();
    }
    cp_wait<STAGES - 2>();
    __syncthreads();

    uint32_t afrag[2][4][4];
    uint32_t bfrag[2][8][2];
    load_frags(sb, sb + A_STAGE_BYTES, 0, afrag[0], bfrag[0]);

    int kc = 0;   // advanced inside chunk_body

    // ---- one K-chunk, fully compile-time specialized ----
    auto chunk_body = [&](auto CSTc, auto LSTc, auto DoLoadC, auto NotLastC) {
        constexpr int  CST     = CSTc.value;               // stage consumed
        constexpr int  LST     = LSTc.value;               // stage filled
        constexpr int  NST     = (CST + 1) % STAGES;       // next consumed stage
        constexpr bool DOLOAD  = DoLoadC.value;
        constexpr bool NOTLAST = NotLastC.value;

        const int  khl = (kc + STAGES - 1) * BK;

        const uint32_t lA = sb + LST * STAGE_BYTES;
        const uint32_t lB = lA + A_STAGE_BYTES;
        const uint32_t sA = sb + CST * STAGE_BYTES;
        const uint32_t sB = sA + A_STAGE_BYTES;
        const uint32_t nA = sb + NST * STAGE_BYTES;
        const uint32_t nB = nA + A_STAGE_BYTES;

        #pragma unroll
        for (int ks = 0; ks < 4; ks++) {
            const int cur = ks & 1;   // compile-time under unroll
            // interleave 4 cp.async (2 A-slices + 2 B-slices) for the prefetch chunk
            if (DOLOAD) {
                #pragma unroll
                for (int q = 0; q < 2; q++) {
                    int r = cp_r0 + (ks * 2 + q) * 16;
                    cp_async16(lA + swz_row_col(r, cp_c * 16),
                               aG + (size_t)r * K_DIM + khl + cp_c * 8);
                    cp_async16(lB + swz_row_col(r, cp_c * 16),
                               bG + (size_t)r * K_DIM + khl + cp_c * 8);
                }
            }

            if (ks < 3) {
                // prefetch next k16 fragments of the current chunk
                load_frags(sA, sB, ks + 1, afrag[cur ^ 1], bfrag[cur ^ 1]);
            } else {
                // chunk boundary: commit, wait, barrier, then prefetch next
                // chunk's ks=0 fragments (stage NST complete after wait<1>)
                cp_commit();
                cp_wait<STAGES - 2>();
                __syncthreads();
                if (NOTLAST)
                    load_frags(nA, nB, 0, afrag[cur ^ 1], bfrag[cur ^ 1]);
            }

            #pragma unroll
            for (int mt = 0; mt < 4; mt++)
                #pragma unroll
                for (int nt = 0; nt < 8; nt++)
                    mma16816(acc[mt][nt], afrag[cur][mt], bfrag[cur][nt]);
        }
        kc++;
    };

    using I0 = std::integral_constant<int, 0>;
    using I1 = std::integral_constant<int, 1>;
    using I2 = std::integral_constant<int, 2>;
    using BT = std::integral_constant<bool, true>;
    using BF = std::integral_constant<bool, false>;

    // chunks 0..59: steady state (load always on)
    #pragma unroll 1
    for (int it = 0; it < 20; it++) {
        chunk_body(I0{}, I2{}, BT{}, BT{});
        chunk_body(I1{}, I0{}, BT{}, BT{});
        chunk_body(I2{}, I1{}, BT{}, BT{});
    }
    // chunks 60-63 peeled: 60,61 load (kload=62,63); 62,63 drain; 63 is last
    chunk_body(I0{}, I2{}, BT{}, BT{});
    chunk_body(I1{}, I0{}, BT{}, BT{});
    chunk_body(I2{}, I1{}, BF{}, BT{});
    chunk_body(I0{}, I2{}, BF{}, BF{});

    // ---- epilogue: scale * acc + bias, streaming (evict-first) float2 stores ----
    const int colbase = tile_n + wn * 64 + (lane & 3) * 2;
    float2 sc[8], bi[8];
    #pragma unroll
    for (int nt = 0; nt < 8; nt++) {
        sc[nt] = *reinterpret_cast<const float2*>(scale + colbase + nt * 8);
        bi[nt] = *reinterpret_cast<const float2*>(bias  + colbase + nt * 8);
    }

    #pragma unroll
    for (int mt = 0; mt < 4; mt++) {
        const int grow = tile_m + wm * 64 + mt * 16 + (lane >> 2);
        float* o0 = out + (size_t)grow * N_DIM + colbase;
        float* o1 = o0 + (size_t)8 * N_DIM;
        #pragma unroll
        for (int nt = 0; nt < 8; nt++) {
            stg_cs_f2(o0 + nt * 8,
                      acc[mt][nt][0] * sc[nt].x + bi[nt].x,
                      acc[mt][nt][1] * sc[nt].y + bi[nt].y);
            stg_cs_f2(o1 + nt * 8,
                      acc[mt][nt][2] * sc[nt].x + bi[nt].x,
                      acc[mt][nt][3] * sc[nt].y + bi[nt].y);
        }
    }
}

// ===================== launch =====================
extern "C" void kernel_launch(void* const* d_in, const int* in_sizes, int n_in,
                              void* d_out, int out_size) {
    const float* inp  = (const float*)d_in[0];   // (4, 2048, 4096) f32
    const int*   wgt  = (const int*)d_in[1];     // (16384, 4096) int32 (int8-valued)
    const float* wsc  = (const float*)d_in[2];   // (16384,) f32
    const float* bias = (const float*)d_in[3];   // (16384,) f32
    float* out = (float*)d_out;                  // (4, 2048, 16384) f32

    (void)in_sizes; (void)n_in; (void)out_size;

    cvt_kernel<<<CVT_A_BLOCKS + CVT_W_BLOCKS, 256>>>(
        reinterpret_cast<const float4*>(inp), reinterpret_cast<const int4*>(wgt));

    cudaFuncSetAttribute(gemm_f16_hmma,
                         cudaFuncAttributeMaxDynamicSharedMemorySize, SMEM_TOTAL);
    gemm_f16_hmma<<<TILES_M * TILES_N, THREADS, SMEM_TOTAL>>>(out, wsc, bias);
}